// round 1
// baseline (speedup 1.0000x reference)
#include <cuda_runtime.h>
#include <cuda_bf16.h>

// ---------------------------------------------------------------------------
// MobileAttention3D: B=2, C=256, D=32, H=W=32, NH=8, KD=VD=64
//
// Pipeline:
//   K1 qkv_gemm : [640x256]@[256x32768] per batch -> Q, K, V' (V pre-shuffled)
//   K2 scores   : A_partial[f-chunk] = Q·K^T  (split-F, no atomics)
//   K2b softmax : reduce partials, scale 1/8, row softmax
//   K3 av       : O' = A @ V'   (writes proj-ready shuffled layout)
//   K4 proj_gemm: [256x512]@[512x32768] per batch * layer_scale
//
// Pixel-shuffle derivation (reference's transpose+reshape):
//   L = n*65536 + h*2048 + w*64 + cv
//   h' = 4n + (h>>3); w' = 4*(h&7) + (w>>3); e = (w&7)*64 + cv
// Baked into V' layout: V'[b][j][e][sigma], sigma = (h>>3)*32 + w' in [0,128)
// Then O'[b][e][d][h'][w'] index = (b*512+e)*32768 + d*1024 + n*128 + sigma.
// ---------------------------------------------------------------------------

#define NPOS 32768   // D*H*W
#define FDIM 65536   // H*W*64

// Scratch (device globals; allocation in kernel_launch is forbidden)
__device__ float g_Q [2*8*32*65536];   // [b][n][i][f], f = c*1024 + s
__device__ float g_K [2*32*65536];     // [b][j][f]
__device__ float g_V [2*32*65536];     // [b][j][e][sigma]  (shuffled)
__device__ float g_Op[2*512*32768];    // [b][e][p']        (proj input)
__device__ float g_Ap[32*16*1024];     // [fchunk][bn][i*32+j] partial logits
__device__ float g_A [16*1024];        // [bn][i*32+j] softmaxed attn

// ---------------------------------------------------------------------------
// K1: QKV GEMM. 128x64 tile, BK=16, 256 threads, 8x4 microtile.
// ---------------------------------------------------------------------------
__global__ __launch_bounds__(256) void qkv_gemm(
    const float* __restrict__ x,
    const float* __restrict__ qw, const float* __restrict__ qb,
    const float* __restrict__ kvw, const float* __restrict__ kvb)
{
    __shared__ float Ws[16][132];
    __shared__ float Xs[16][68];
    const int tid = threadIdx.x;
    const int tx = tid & 15, ty = tid >> 4;
    const int p0  = blockIdx.x * 64;
    const int oc0 = blockIdx.y * 128;
    const int b   = blockIdx.z;
    const float* xb = x + (size_t)b * 256 * NPOS;

    float acc[8][4];
#pragma unroll
    for (int mi = 0; mi < 8; mi++)
#pragma unroll
        for (int ni = 0; ni < 4; ni++) acc[mi][ni] = 0.f;

    for (int kt = 0; kt < 256; kt += 16) {
#pragma unroll
        for (int l = 0; l < 8; l++) {
            int e = l * 256 + tid;
            int kk = e & 15, mm = e >> 4;
            int oc = oc0 + mm;
            Ws[kk][mm] = (oc < 512) ? qw[oc * 256 + kt + kk]
                                    : kvw[(oc - 512) * 256 + kt + kk];
        }
#pragma unroll
        for (int l = 0; l < 4; l++) {
            int e = l * 256 + tid;
            int kk = e >> 6, nn = e & 63;
            Xs[kk][nn] = xb[(kt + kk) * NPOS + p0 + nn];
        }
        __syncthreads();
#pragma unroll
        for (int k = 0; k < 16; k++) {
            float4 a0 = *(const float4*)&Ws[k][ty * 8];
            float4 a1 = *(const float4*)&Ws[k][ty * 8 + 4];
            float4 bv = *(const float4*)&Xs[k][tx * 4];
            float am[8] = {a0.x,a0.y,a0.z,a0.w,a1.x,a1.y,a1.z,a1.w};
            float bm[4] = {bv.x,bv.y,bv.z,bv.w};
#pragma unroll
            for (int mi = 0; mi < 8; mi++)
#pragma unroll
                for (int ni = 0; ni < 4; ni++)
                    acc[mi][ni] += am[mi] * bm[ni];
        }
        __syncthreads();
    }

#pragma unroll
    for (int mi = 0; mi < 8; mi++) {
        int oc = oc0 + ty * 8 + mi;
        float bias = (oc < 512) ? qb[oc] : kvb[oc - 512];
#pragma unroll
        for (int ni = 0; ni < 4; ni++) {
            int p = p0 + tx * 4 + ni;
            float v = acc[mi][ni] + bias;
            int i = p >> 10, s = p & 1023;
            if (oc < 512) {
                int n = oc >> 6, c = oc & 63;
                g_Q[(((unsigned)(b * 8 + n) * 32 + i) << 16) + (c << 10) + s] = v;
            } else if (oc < 576) {
                int c = oc - 512;
                g_K[(((unsigned)(b * 32 + i)) << 16) + (c << 10) + s] = v;
            } else {
                int cv = oc - 576;
                int h = s >> 5, w = s & 31;
                int e2  = ((w & 7) << 6) | cv;
                int sig = ((h >> 3) << 5) | ((h & 7) << 2) | (w >> 3);
                g_V[(((unsigned)(b * 32 + i)) << 16) + (e2 << 7) + sig] = v;
            }
        }
    }
}

// ---------------------------------------------------------------------------
// K2: attention logits, split over F into 32 chunks of 2048.
// Block = 256 threads, each owns a 2x2 of the 32x32 logit tile.
// ---------------------------------------------------------------------------
__global__ __launch_bounds__(256) void scores_kernel()
{
    __shared__ float Qs[32][33];
    __shared__ float Ks[32][33];
    const int tid = threadIdx.x;
    const int j0 = (tid & 15) * 2;
    const int i0 = (tid >> 4) * 2;
    const int bn = blockIdx.y;
    const int b  = bn >> 3;
    const unsigned qbase = (unsigned)bn * 32u * 65536u;
    const unsigned kbase = (unsigned)b  * 32u * 65536u;
    const int f0 = blockIdx.x * 2048;

    float a00 = 0.f, a01 = 0.f, a10 = 0.f, a11 = 0.f;
    for (int fb = f0; fb < f0 + 2048; fb += 32) {
#pragma unroll
        for (int l = 0; l < 4; l++) {
            int e = l * 256 + tid;
            int r = e >> 5, c = e & 31;
            Qs[r][c] = g_Q[qbase + ((unsigned)r << 16) + fb + c];
            Ks[r][c] = g_K[kbase + ((unsigned)r << 16) + fb + c];
        }
        __syncthreads();
#pragma unroll
        for (int k = 0; k < 32; k++) {
            float q0 = Qs[i0][k],   q1 = Qs[i0 + 1][k];
            float k0 = Ks[j0][k],   k1 = Ks[j0 + 1][k];
            a00 += q0 * k0; a01 += q0 * k1;
            a10 += q1 * k0; a11 += q1 * k1;
        }
        __syncthreads();
    }
    unsigned abase = (unsigned)(blockIdx.x * 16 + bn) * 1024u;
    g_Ap[abase +  i0      * 32 + j0    ] = a00;
    g_Ap[abase +  i0      * 32 + j0 + 1] = a01;
    g_Ap[abase + (i0 + 1) * 32 + j0    ] = a10;
    g_Ap[abase + (i0 + 1) * 32 + j0 + 1] = a11;
}

// ---------------------------------------------------------------------------
// K2b: reduce 32 partials, scale by 1/8, softmax along j (warp = row).
// ---------------------------------------------------------------------------
__global__ __launch_bounds__(1024) void softmax_kernel()
{
    const int bn = blockIdx.x;
    const int tid = threadIdx.x;
    const int i = tid >> 5, j = tid & 31;

    float v = 0.f;
#pragma unroll
    for (int c = 0; c < 32; c++)
        v += g_Ap[((unsigned)(c * 16 + bn) << 10) + (i << 5) + j];
    v *= 0.125f;  // VD^-0.5

    float m = v;
#pragma unroll
    for (int o = 16; o; o >>= 1) m = fmaxf(m, __shfl_xor_sync(0xffffffffu, m, o));
    float e = expf(v - m);
    float s = e;
#pragma unroll
    for (int o = 16; o; o >>= 1) s += __shfl_xor_sync(0xffffffffu, s, o);
    g_A[((unsigned)bn << 10) + (i << 5) + j] = e / s;
}

// ---------------------------------------------------------------------------
// K3: O' = A @ V'. grid (32 e-tiles of 16, 16 bn). 256 threads handle 2 e's
// at a time: thread -> (e-half, sigma). Coalesced V' reads and O' writes.
// ---------------------------------------------------------------------------
__global__ __launch_bounds__(256) void av_kernel()
{
    __shared__ float As[1024];
    __shared__ float Vs[2][32][128];
    const int tid = threadIdx.x;
    const int bn = blockIdx.y;
    const int b = bn >> 3, n = bn & 7;
    const int e0 = blockIdx.x * 16;

#pragma unroll
    for (int l = 0; l < 4; l++)
        As[l * 256 + tid] = g_A[((unsigned)bn << 10) + l * 256 + tid];
    __syncthreads();

    const int eh  = tid >> 7;
    const int sig = tid & 127;
    const unsigned vbase = ((unsigned)(b * 32)) << 16;

    for (int ei = 0; ei < 16; ei += 2) {
        const int e = e0 + ei + eh;
#pragma unroll
        for (int j = 0; j < 32; j++)
            Vs[eh][j][sig] = g_V[vbase + ((unsigned)j << 16) + (e << 7) + sig];
        __syncthreads();

        float acc[32];
#pragma unroll
        for (int i = 0; i < 32; i++) acc[i] = 0.f;
#pragma unroll
        for (int j = 0; j < 32; j++) {
            float v = Vs[eh][j][sig];
#pragma unroll
            for (int i = 0; i < 32; i++)
                acc[i] += As[(i << 5) + j] * v;
        }
        const unsigned obase = ((unsigned)(b * 512 + e) << 15) + (n << 7) + sig;
#pragma unroll
        for (int i = 0; i < 32; i++)
            g_Op[obase + (i << 10)] = acc[i];
        __syncthreads();
    }
}

// ---------------------------------------------------------------------------
// K4: proj GEMM [256x512]@[512x32768] per batch, fused bias + layer_scale.
// ---------------------------------------------------------------------------
__global__ __launch_bounds__(256) void proj_gemm(
    const float* __restrict__ pw, const float* __restrict__ pb,
    const float* __restrict__ ls, float* __restrict__ out)
{
    __shared__ float Ws[16][132];
    __shared__ float Xs[16][68];
    const int tid = threadIdx.x;
    const int tx = tid & 15, ty = tid >> 4;
    const int p0  = blockIdx.x * 64;
    const int oc0 = blockIdx.y * 128;
    const int b   = blockIdx.z;

    float acc[8][4];
#pragma unroll
    for (int mi = 0; mi < 8; mi++)
#pragma unroll
        for (int ni = 0; ni < 4; ni++) acc[mi][ni] = 0.f;

    for (int kt = 0; kt < 512; kt += 16) {
#pragma unroll
        for (int l = 0; l < 8; l++) {
            int e = l * 256 + tid;
            int kk = e & 15, mm = e >> 4;
            Ws[kk][mm] = pw[(oc0 + mm) * 512 + kt + kk];
        }
#pragma unroll
        for (int l = 0; l < 4; l++) {
            int e = l * 256 + tid;
            int kk = e >> 6, nn = e & 63;
            Xs[kk][nn] = g_Op[((unsigned)(b * 512 + kt + kk) << 15) + p0 + nn];
        }
        __syncthreads();
#pragma unroll
        for (int k = 0; k < 16; k++) {
            float4 a0 = *(const float4*)&Ws[k][ty * 8];
            float4 a1 = *(const float4*)&Ws[k][ty * 8 + 4];
            float4 bv = *(const float4*)&Xs[k][tx * 4];
            float am[8] = {a0.x,a0.y,a0.z,a0.w,a1.x,a1.y,a1.z,a1.w};
            float bm[4] = {bv.x,bv.y,bv.z,bv.w};
#pragma unroll
            for (int mi = 0; mi < 8; mi++)
#pragma unroll
                for (int ni = 0; ni < 4; ni++)
                    acc[mi][ni] += am[mi] * bm[ni];
        }
        __syncthreads();
    }

#pragma unroll
    for (int mi = 0; mi < 8; mi++) {
        int oc = oc0 + ty * 8 + mi;
        float bias = pb[oc];
        float scale = ls[oc];
#pragma unroll
        for (int ni = 0; ni < 4; ni++) {
            int p = p0 + tx * 4 + ni;
            out[((unsigned)(b * 256 + oc) << 15) + p] = (acc[mi][ni] + bias) * scale;
        }
    }
}

// ---------------------------------------------------------------------------
extern "C" void kernel_launch(void* const* d_in, const int* in_sizes, int n_in,
                              void* d_out, int out_size)
{
    (void)in_sizes; (void)n_in; (void)out_size;
    const float* x   = (const float*)d_in[0];
    const float* qw  = (const float*)d_in[1];
    const float* qb  = (const float*)d_in[2];
    const float* kvw = (const float*)d_in[3];
    const float* kvb = (const float*)d_in[4];
    const float* pw  = (const float*)d_in[5];
    const float* pb  = (const float*)d_in[6];
    const float* ls  = (const float*)d_in[7];
    float* out = (float*)d_out;

    qkv_gemm   <<<dim3(512, 5, 2), 256>>>(x, qw, qb, kvw, kvb);
    scores_kernel<<<dim3(32, 16),  256>>>();
    softmax_kernel<<<16, 1024>>>();
    av_kernel  <<<dim3(32, 16),  256>>>();
    proj_gemm  <<<dim3(512, 2, 2), 256>>>(pw, pb, ls, out);
}

// round 3
// speedup vs baseline: 1.4550x; 1.4550x over previous
#include <cuda_runtime.h>
#include <cuda_bf16.h>
#include <cstdint>

// ---------------------------------------------------------------------------
// MobileAttention3D: B=2, C=256, D=32, H=W=32, NH=8, KD=VD=64
//
// R3: conv GEMMs on warp-level mma.sync (HMMA bf16, sm_103-safe, no 'a' feats)
//   K0 cvt_x   : x fp32 -> packed bf16 hi/lo, channel-pair-major
//   K1 qkv_mma : [640x256]@[256x32768]/b -> Q,K,V' (V pixel-shuffled)
//   K2 scores  : Q·K^T split-F logits
//   K2b softmax
//   K3 av      : O' = A@V', emits proj input as packed bf16 hi/lo
//   K4 proj_mma: [256x512]@[512x32768]/b + bias + layer_scale
// bf16 2-term split (hi+lo), 3 MMAs per tile, fp32 accum => ~1e-5 rel err.
// ---------------------------------------------------------------------------

#define NPOS 32768

__device__ float    g_Q  [2*8*32*65536];  // [b][n][i][f], f=c*1024+s
__device__ float    g_K  [2*32*65536];    // [b][j][f]
__device__ float    g_V  [2*32*65536];    // [b][j][e][sigma] (shuffled)
__device__ float    g_Ap [32*16*1024];    // partial logits
__device__ float    g_A  [16*1024];       // softmaxed attn
__device__ uint32_t g_xph[2*128*32768];   // x bf16-hi pairs [b][cp][p]
__device__ uint32_t g_xpl[2*128*32768];   // x bf16-lo pairs
__device__ uint32_t g_oph[2*256*32768];   // proj-input hi pairs [b][ep][p']
__device__ uint32_t g_opl[2*256*32768];   // proj-input lo pairs

// ---- helpers ----
__device__ __forceinline__ void pack2(float a, float b, uint32_t& hi, uint32_t& lo) {
    __nv_bfloat16 ah = __float2bfloat16(a), bh = __float2bfloat16(b);
    float ar = a - __bfloat162float(ah), br = b - __bfloat162float(bh);
    __nv_bfloat16 al = __float2bfloat16(ar), bl = __float2bfloat16(br);
    hi = (uint32_t)__bfloat16_as_ushort(ah) | ((uint32_t)__bfloat16_as_ushort(bh) << 16);
    lo = (uint32_t)__bfloat16_as_ushort(al) | ((uint32_t)__bfloat16_as_ushort(bl) << 16);
}

#define MMA16816(d, a, bf) \
    asm volatile("mma.sync.aligned.m16n8k16.row.col.f32.bf16.bf16.f32 " \
        "{%0,%1,%2,%3}, {%4,%5,%6,%7}, {%8,%9}, {%0,%1,%2,%3};" \
        : "+f"((d)[0]), "+f"((d)[1]), "+f"((d)[2]), "+f"((d)[3]) \
        : "r"((a)[0]), "r"((a)[1]), "r"((a)[2]), "r"((a)[3]), \
          "r"((bf)[0]), "r"((bf)[1]))

// ---------------------------------------------------------------------------
// K0: convert x to packed bf16 hi/lo, pair over adjacent channels.
// grid (32 pos-chunks, 128 cp, 2 b), 256 threads.
// ---------------------------------------------------------------------------
__global__ __launch_bounds__(256) void cvt_x(const float* __restrict__ x)
{
    const int p  = blockIdx.x * 1024 + threadIdx.x * 4;
    const int cp = blockIdx.y;
    const int b  = blockIdx.z;
    const float4 x0 = *(const float4*)&x[((size_t)(b * 256 + 2*cp    ) << 15) + p];
    const float4 x1 = *(const float4*)&x[((size_t)(b * 256 + 2*cp + 1) << 15) + p];
    uint4 h, l;
    pack2(x0.x, x1.x, h.x, l.x);
    pack2(x0.y, x1.y, h.y, l.y);
    pack2(x0.z, x1.z, h.z, l.z);
    pack2(x0.w, x1.w, h.w, l.w);
    const size_t o = ((size_t)(b * 128 + cp) << 15) + p;
    *(uint4*)&g_xph[o] = h;
    *(uint4*)&g_xpl[o] = l;
}

// ---------------------------------------------------------------------------
// Scatter store for qkv epilogue (same mapping as the validated R1 kernel).
// ---------------------------------------------------------------------------
__device__ __forceinline__ void store_qkv(int b, int oc, int p, float val,
                                          const float* qb, const float* kvb)
{
    const int i = p >> 10, ssp = p & 1023;
    if (oc < 512) {
        val += qb[oc];
        const int n = oc >> 6, cq = oc & 63;
        g_Q[(((unsigned)(b * 8 + n) * 32 + i) << 16) + (cq << 10) + ssp] = val;
    } else if (oc < 576) {
        val += kvb[oc - 512];
        g_K[(((unsigned)(b * 32 + i)) << 16) + ((oc - 512) << 10) + ssp] = val;
    } else {
        val += kvb[oc - 512];
        const int cv = oc - 576;
        const int h = ssp >> 5, w = ssp & 31;
        const int e2  = ((w & 7) << 6) | cv;
        const int sig = ((h >> 3) << 5) | ((h & 7) << 2) | (w >> 3);
        g_V[(((unsigned)(b * 32 + i)) << 16) + (e2 << 7) + sig] = val;
    }
}

// ---------------------------------------------------------------------------
// K1: QKV GEMM via mma.sync. grid(256 p-tiles, 2 b), 256 thr (8 warps 2x4).
// Block tile 128oc x 128pos per chunk, 5 oc chunks, K=256 in 16-steps.
// ---------------------------------------------------------------------------
__global__ __launch_bounds__(256) void qkv_mma(
    const float* __restrict__ qw, const float* __restrict__ qb,
    const float* __restrict__ kvw, const float* __restrict__ kvb)
{
    __shared__ uint32_t Awh[8][136], Awl[8][136], Bxh[8][136], Bxl[8][136];
    const int tid = threadIdx.x, lane = tid & 31, wid = tid >> 5;
    const int wm = wid & 1, wn = wid >> 1;
    const int g = lane >> 2, t = lane & 3;
    const int p0 = blockIdx.x * 128, b = blockIdx.y;

    const int oc_l = tid & 127, half = tid >> 7;
    const int kp_x = tid >> 5;

    for (int mc = 0; mc < 5; mc++) {
        float acc[4][4][4];
#pragma unroll
        for (int mb = 0; mb < 4; mb++)
#pragma unroll
            for (int nb = 0; nb < 4; nb++)
#pragma unroll
                for (int r = 0; r < 4; r++) acc[mb][nb][r] = 0.f;

        for (int s = 0; s < 16; s++) {
            // W tile: 128 oc x 16 k
            {
                const int oc = mc * 128 + oc_l;
                const float* wr = (oc < 512) ? qw + (size_t)oc * 256
                                             : kvw + (size_t)(oc - 512) * 256;
                const int k0 = s * 16 + half * 8;
                const float4 f0 = *(const float4*)(wr + k0);
                const float4 f1 = *(const float4*)(wr + k0 + 4);
                uint32_t h0,l0,h1,l1,h2,l2,h3,l3;
                pack2(f0.x, f0.y, h0, l0); pack2(f0.z, f0.w, h1, l1);
                pack2(f1.x, f1.y, h2, l2); pack2(f1.z, f1.w, h3, l3);
                Awh[half*4+0][oc_l] = h0; Awh[half*4+1][oc_l] = h1;
                Awh[half*4+2][oc_l] = h2; Awh[half*4+3][oc_l] = h3;
                Awl[half*4+0][oc_l] = l0; Awl[half*4+1][oc_l] = l1;
                Awl[half*4+2][oc_l] = l2; Awl[half*4+3][oc_l] = l3;
            }
            // X tile: 16 k x 128 pos (pre-packed)
            {
                const size_t o = ((size_t)(b * 128 + s * 8 + kp_x) << 15) + p0 + lane * 4;
                *(uint4*)&Bxh[kp_x][lane*4] = *(const uint4*)&g_xph[o];
                *(uint4*)&Bxl[kp_x][lane*4] = *(const uint4*)&g_xpl[o];
            }
            __syncthreads();

            uint32_t bh[4][2], bl[4][2];
#pragma unroll
            for (int nb = 0; nb < 4; nb++) {
                const int nbase = wn * 32 + nb * 8 + g;
                bh[nb][0] = Bxh[t][nbase];     bh[nb][1] = Bxh[t+4][nbase];
                bl[nb][0] = Bxl[t][nbase];     bl[nb][1] = Bxl[t+4][nbase];
            }
#pragma unroll
            for (int mb = 0; mb < 4; mb++) {
                const int mbase = wm * 64 + mb * 16 + g;
                uint32_t ah[4], al_[4];
                ah[0] = Awh[t][mbase];    ah[1] = Awh[t][mbase+8];
                ah[2] = Awh[t+4][mbase];  ah[3] = Awh[t+4][mbase+8];
                al_[0] = Awl[t][mbase];   al_[1] = Awl[t][mbase+8];
                al_[2] = Awl[t+4][mbase]; al_[3] = Awl[t+4][mbase+8];
#pragma unroll
                for (int nb = 0; nb < 4; nb++) {
                    MMA16816(acc[mb][nb], ah,  bh[nb]);
                    MMA16816(acc[mb][nb], ah,  bl[nb]);
                    MMA16816(acc[mb][nb], al_, bh[nb]);
                }
            }
            __syncthreads();
        }
        // epilogue: scatter
#pragma unroll
        for (int mb = 0; mb < 4; mb++) {
            const int oc_a = mc * 128 + wm * 64 + mb * 16 + g;
#pragma unroll
            for (int nb = 0; nb < 4; nb++) {
                const int pos_a = p0 + wn * 32 + nb * 8 + t * 2;
                store_qkv(b, oc_a,     pos_a,     acc[mb][nb][0], qb, kvb);
                store_qkv(b, oc_a,     pos_a + 1, acc[mb][nb][1], qb, kvb);
                store_qkv(b, oc_a + 8, pos_a,     acc[mb][nb][2], qb, kvb);
                store_qkv(b, oc_a + 8, pos_a + 1, acc[mb][nb][3], qb, kvb);
            }
        }
    }
}

// ---------------------------------------------------------------------------
// K2: attention logits, split over F into 32 chunks of 2048.
// ---------------------------------------------------------------------------
__global__ __launch_bounds__(256) void scores_kernel()
{
    __shared__ __align__(16) float Qs[32][36];
    __shared__ __align__(16) float Ks[32][36];
    const int tid = threadIdx.x;
    const int j0 = (tid & 15) * 2;
    const int i0 = (tid >> 4) * 2;
    const int bn = blockIdx.y;
    const int b  = bn >> 3;
    const unsigned qbase = (unsigned)bn * 32u * 65536u;
    const unsigned kbase = (unsigned)b  * 32u * 65536u;
    const int f0 = blockIdx.x * 2048;
    const int lr = tid >> 3, lc = (tid & 7) * 4;

    float a00 = 0.f, a01 = 0.f, a10 = 0.f, a11 = 0.f;
    for (int fb = f0; fb < f0 + 2048; fb += 32) {
        *(float4*)&Qs[lr][lc] = *(const float4*)&g_Q[qbase + ((unsigned)lr << 16) + fb + lc];
        *(float4*)&Ks[lr][lc] = *(const float4*)&g_K[kbase + ((unsigned)lr << 16) + fb + lc];
        __syncthreads();
#pragma unroll
        for (int k = 0; k < 32; k += 4) {
            float4 q0 = *(const float4*)&Qs[i0][k];
            float4 q1 = *(const float4*)&Qs[i0 + 1][k];
            float4 k0 = *(const float4*)&Ks[j0][k];
            float4 k1 = *(const float4*)&Ks[j0 + 1][k];
            a00 += q0.x*k0.x + q0.y*k0.y + q0.z*k0.z + q0.w*k0.w;
            a01 += q0.x*k1.x + q0.y*k1.y + q0.z*k1.z + q0.w*k1.w;
            a10 += q1.x*k0.x + q1.y*k0.y + q1.z*k0.z + q1.w*k0.w;
            a11 += q1.x*k1.x + q1.y*k1.y + q1.z*k1.z + q1.w*k1.w;
        }
        __syncthreads();
    }
    const unsigned abase = (unsigned)(blockIdx.x * 16 + bn) * 1024u;
    g_Ap[abase +  i0      * 32 + j0    ] = a00;
    g_Ap[abase +  i0      * 32 + j0 + 1] = a01;
    g_Ap[abase + (i0 + 1) * 32 + j0    ] = a10;
    g_Ap[abase + (i0 + 1) * 32 + j0 + 1] = a11;
}

// ---------------------------------------------------------------------------
__global__ __launch_bounds__(1024) void softmax_kernel()
{
    const int bn = blockIdx.x;
    const int tid = threadIdx.x;
    const int i = tid >> 5, j = tid & 31;
    float v = 0.f;
#pragma unroll
    for (int c = 0; c < 32; c++)
        v += g_Ap[((unsigned)(c * 16 + bn) << 10) + (i << 5) + j];
    v *= 0.125f;
    float m = v;
#pragma unroll
    for (int o = 16; o; o >>= 1) m = fmaxf(m, __shfl_xor_sync(0xffffffffu, m, o));
    float e = expf(v - m);
    float s = e;
#pragma unroll
    for (int o = 16; o; o >>= 1) s += __shfl_xor_sync(0xffffffffu, s, o);
    g_A[((unsigned)bn << 10) + (i << 5) + j] = e / s;
}

// ---------------------------------------------------------------------------
// K3: O' = A @ V'.  Writes proj input directly as packed bf16 hi/lo pairs
// (adjacent e channels paired via smem exchange).
// ---------------------------------------------------------------------------
__global__ __launch_bounds__(256) void av_kernel()
{
    __shared__ __align__(16) float As[1024];
    __shared__ float Vs[2][32][128];
    const int tid = threadIdx.x;
    const int bn = blockIdx.y;
    const int b = bn >> 3, n = bn & 7;
    const int e0 = blockIdx.x * 16;

#pragma unroll
    for (int l = 0; l < 4; l++)
        As[l * 256 + tid] = g_A[((unsigned)bn << 10) + l * 256 + tid];
    __syncthreads();

    const int eh  = tid >> 7;
    const int sig = tid & 127;
    const unsigned vbase = ((unsigned)(b * 32)) << 16;

    for (int ei = 0; ei < 16; ei += 2) {
        const int e = e0 + ei + eh;
#pragma unroll
        for (int j = 0; j < 32; j++)
            Vs[eh][j][sig] = g_V[vbase + ((unsigned)j << 16) + (e << 7) + sig];
        __syncthreads();

        float v[32];
#pragma unroll
        for (int j = 0; j < 32; j++) v[j] = Vs[eh][j][sig];

        float acc[32];
#pragma unroll
        for (int i = 0; i < 32; i++) acc[i] = 0.f;
#pragma unroll
        for (int i = 0; i < 32; i++) {
#pragma unroll
            for (int j4 = 0; j4 < 8; j4++) {
                const float4 a = *(const float4*)&As[(i << 5) + j4 * 4];
                acc[i] += a.x * v[j4*4] + a.y * v[j4*4+1] + a.z * v[j4*4+2] + a.w * v[j4*4+3];
            }
        }
        __syncthreads();          // all Vs reads done
#pragma unroll
        for (int i = 0; i < 32; i++) Vs[eh][i][sig] = acc[i];
        __syncthreads();

        // pack pairs (e0+ei, e0+ei+1) -> g_oph/g_opl
        const int ep = (e0 + ei) >> 1;
        const size_t obase = ((size_t)(b * 256 + ep) << 15) + (n << 7) + sig;
#pragma unroll
        for (int ii = 0; ii < 16; ii++) {
            const int i = eh * 16 + ii;
            uint32_t h, l;
            pack2(Vs[0][i][sig], Vs[1][i][sig], h, l);
            g_oph[obase + ((size_t)i << 10)] = h;
            g_opl[obase + ((size_t)i << 10)] = l;
        }
        __syncthreads();
    }
}

// ---------------------------------------------------------------------------
// K4: proj GEMM via mma.sync. grid(256 p-tiles, 2 b), 256 threads.
// M=256 (2 chunks of 128), K=512 (32 k-steps), N=128 pos.
// ---------------------------------------------------------------------------
__global__ __launch_bounds__(256) void proj_mma(
    const float* __restrict__ pw, const float* __restrict__ pb,
    const float* __restrict__ ls, float* __restrict__ out)
{
    __shared__ uint32_t Awh[8][136], Awl[8][136], Bxh[8][136], Bxl[8][136];
    const int tid = threadIdx.x, lane = tid & 31, wid = tid >> 5;
    const int wm = wid & 1, wn = wid >> 1;
    const int g = lane >> 2, t = lane & 3;
    const int p0 = blockIdx.x * 128, b = blockIdx.y;

    const int oc_l = tid & 127, half = tid >> 7;
    const int kp_x = tid >> 5;

    for (int mc = 0; mc < 2; mc++) {
        float acc[4][4][4];
#pragma unroll
        for (int mb = 0; mb < 4; mb++)
#pragma unroll
            for (int nb = 0; nb < 4; nb++)
#pragma unroll
                for (int r = 0; r < 4; r++) acc[mb][nb][r] = 0.f;

        for (int s = 0; s < 32; s++) {
            {
                const int oc = mc * 128 + oc_l;
                const float* wr = pw + (size_t)oc * 512;
                const int k0 = s * 16 + half * 8;
                const float4 f0 = *(const float4*)(wr + k0);
                const float4 f1 = *(const float4*)(wr + k0 + 4);
                uint32_t h0,l0,h1,l1,h2,l2,h3,l3;
                pack2(f0.x, f0.y, h0, l0); pack2(f0.z, f0.w, h1, l1);
                pack2(f1.x, f1.y, h2, l2); pack2(f1.z, f1.w, h3, l3);
                Awh[half*4+0][oc_l] = h0; Awh[half*4+1][oc_l] = h1;
                Awh[half*4+2][oc_l] = h2; Awh[half*4+3][oc_l] = h3;
                Awl[half*4+0][oc_l] = l0; Awl[half*4+1][oc_l] = l1;
                Awl[half*4+2][oc_l] = l2; Awl[half*4+3][oc_l] = l3;
            }
            {
                const size_t o = ((size_t)(b * 256 + s * 8 + kp_x) << 15) + p0 + lane * 4;
                *(uint4*)&Bxh[kp_x][lane*4] = *(const uint4*)&g_oph[o];
                *(uint4*)&Bxl[kp_x][lane*4] = *(const uint4*)&g_opl[o];
            }
            __syncthreads();

            uint32_t bh[4][2], bl[4][2];
#pragma unroll
            for (int nb = 0; nb < 4; nb++) {
                const int nbase = wn * 32 + nb * 8 + g;
                bh[nb][0] = Bxh[t][nbase];   bh[nb][1] = Bxh[t+4][nbase];
                bl[nb][0] = Bxl[t][nbase];   bl[nb][1] = Bxl[t+4][nbase];
            }
#pragma unroll
            for (int mb = 0; mb < 4; mb++) {
                const int mbase = wm * 64 + mb * 16 + g;
                uint32_t ah[4], al_[4];
                ah[0] = Awh[t][mbase];    ah[1] = Awh[t][mbase+8];
                ah[2] = Awh[t+4][mbase];  ah[3] = Awh[t+4][mbase+8];
                al_[0] = Awl[t][mbase];   al_[1] = Awl[t][mbase+8];
                al_[2] = Awl[t+4][mbase]; al_[3] = Awl[t+4][mbase+8];
#pragma unroll
                for (int nb = 0; nb < 4; nb++) {
                    MMA16816(acc[mb][nb], ah,  bh[nb]);
                    MMA16816(acc[mb][nb], ah,  bl[nb]);
                    MMA16816(acc[mb][nb], al_, bh[nb]);
                }
            }
            __syncthreads();
        }
#pragma unroll
        for (int mb = 0; mb < 4; mb++) {
            const int r0 = mc * 128 + wm * 64 + mb * 16 + g;
            const float b0 = pb[r0], s0 = ls[r0];
            const float b1 = pb[r0 + 8], s1 = ls[r0 + 8];
#pragma unroll
            for (int nb = 0; nb < 4; nb++) {
                const int pos_a = p0 + wn * 32 + nb * 8 + t * 2;
                float* o0 = out + (((size_t)(b * 256 + r0)) << 15) + pos_a;
                float* o1 = out + (((size_t)(b * 256 + r0 + 8)) << 15) + pos_a;
                o0[0] = (acc[mb][nb][0] + b0) * s0;
                o0[1] = (acc[mb][nb][1] + b0) * s0;
                o1[0] = (acc[mb][nb][2] + b1) * s1;
                o1[1] = (acc[mb][nb][3] + b1) * s1;
            }
        }
    }
}

// ---------------------------------------------------------------------------
extern "C" void kernel_launch(void* const* d_in, const int* in_sizes, int n_in,
                              void* d_out, int out_size)
{
    (void)in_sizes; (void)n_in; (void)out_size;
    const float* x   = (const float*)d_in[0];
    const float* qw  = (const float*)d_in[1];
    const float* qb  = (const float*)d_in[2];
    const float* kvw = (const float*)d_in[3];
    const float* kvb = (const float*)d_in[4];
    const float* pw  = (const float*)d_in[5];
    const float* pb  = (const float*)d_in[6];
    const float* ls  = (const float*)d_in[7];
    float* out = (float*)d_out;

    cvt_x         <<<dim3(32, 128, 2), 256>>>(x);
    qkv_mma       <<<dim3(256, 2), 256>>>(qw, qb, kvw, kvb);
    scores_kernel <<<dim3(32, 16), 256>>>();
    softmax_kernel<<<16, 1024>>>();
    av_kernel     <<<dim3(32, 16), 256>>>();
    proj_mma      <<<dim3(256, 2), 256>>>(pw, pb, ls, out);
}

// round 4
// speedup vs baseline: 1.9808x; 1.3614x over previous
#include <cuda_runtime.h>
#include <cuda_bf16.h>
#include <cstdint>

// ---------------------------------------------------------------------------
// MobileAttention3D: B=2, C=256, D=32, H=W=32, NH=8, KD=VD=64
//
// R4: GEMM pipeline hygiene.
//   - weights pre-packed to bf16 hi/lo (k-pair-major) once, outside hot loop
//   - cp.async double-buffered W/X tiles, 1 syncthreads per k-step
//   K0 cvt_x / pack_w ; K1 qkv_mma ; K2 scores ; K2b softmax ; K3 av ;
//   K4 proj_mma
// bf16 2-term split (hi+lo), 3 MMAs per tile, fp32 accum => ~1e-5 rel err.
// ---------------------------------------------------------------------------

#define NPOS 32768

__device__ float    g_Q  [2*8*32*65536];  // [b][n][i][f], f=c*1024+s
__device__ float    g_K  [2*32*65536];    // [b][j][f]
__device__ float    g_V  [2*32*65536];    // [b][j][e][sigma] (shuffled)
__device__ float    g_Ap [32*16*1024];    // partial logits
__device__ float    g_A  [16*1024];       // softmaxed attn
__device__ uint32_t g_xph[2*128*32768];   // x bf16-hi pairs [b][cp][p]
__device__ uint32_t g_xpl[2*128*32768];   // x bf16-lo pairs
__device__ uint32_t g_oph[2*256*32768];   // proj-input hi pairs [b][ep][p']
__device__ uint32_t g_opl[2*256*32768];   // proj-input lo pairs
__device__ uint32_t g_wqh[128*640];       // qkv W hi pairs [kp][oc]
__device__ uint32_t g_wql[128*640];
__device__ uint32_t g_wph[256*256];       // proj W hi pairs [kp][oc]
__device__ uint32_t g_wpl[256*256];

// ---- helpers ----
__device__ __forceinline__ void pack2(float a, float b, uint32_t& hi, uint32_t& lo) {
    __nv_bfloat16 ah = __float2bfloat16(a), bh = __float2bfloat16(b);
    float ar = a - __bfloat162float(ah), br = b - __bfloat162float(bh);
    __nv_bfloat16 al = __float2bfloat16(ar), bl = __float2bfloat16(br);
    hi = (uint32_t)__bfloat16_as_ushort(ah) | ((uint32_t)__bfloat16_as_ushort(bh) << 16);
    lo = (uint32_t)__bfloat16_as_ushort(al) | ((uint32_t)__bfloat16_as_ushort(bl) << 16);
}

__device__ __forceinline__ uint32_t smem_u32(const void* p) {
    uint32_t a;
    asm("{ .reg .u64 t; cvta.to.shared.u64 t, %1; cvt.u32.u64 %0, t; }" : "=r"(a) : "l"(p));
    return a;
}

#define MMA16816(d, a, bf) \
    asm volatile("mma.sync.aligned.m16n8k16.row.col.f32.bf16.bf16.f32 " \
        "{%0,%1,%2,%3}, {%4,%5,%6,%7}, {%8,%9}, {%0,%1,%2,%3};" \
        : "+f"((d)[0]), "+f"((d)[1]), "+f"((d)[2]), "+f"((d)[3]) \
        : "r"((a)[0]), "r"((a)[1]), "r"((a)[2]), "r"((a)[3]), \
          "r"((bf)[0]), "r"((bf)[1]))

#define CP16(dst, src) \
    asm volatile("cp.async.cg.shared.global [%0], [%1], 16;" :: "r"(dst), "l"(src) : "memory")
#define CP_COMMIT() asm volatile("cp.async.commit_group;" ::: "memory")
#define CP_WAIT0()  asm volatile("cp.async.wait_group 0;" ::: "memory")

// smem tile geometry: [buf][arr][8][136] uint32
#define ROWW 136
#define AOFF (8*ROWW*4)       // bytes per array
#define BUFOFF (4*AOFF)       // bytes per buffer (4 arrays)

// ---------------------------------------------------------------------------
// K0a: convert x to packed bf16 hi/lo pairs over adjacent channels.
// ---------------------------------------------------------------------------
__global__ __launch_bounds__(256) void cvt_x(const float* __restrict__ x)
{
    const int p  = blockIdx.x * 1024 + threadIdx.x * 4;
    const int cp = blockIdx.y;
    const int b  = blockIdx.z;
    const float4 x0 = *(const float4*)&x[((size_t)(b * 256 + 2*cp    ) << 15) + p];
    const float4 x1 = *(const float4*)&x[((size_t)(b * 256 + 2*cp + 1) << 15) + p];
    uint4 h, l;
    pack2(x0.x, x1.x, h.x, l.x);
    pack2(x0.y, x1.y, h.y, l.y);
    pack2(x0.z, x1.z, h.z, l.z);
    pack2(x0.w, x1.w, h.w, l.w);
    const size_t o = ((size_t)(b * 128 + cp) << 15) + p;
    *(uint4*)&g_xph[o] = h;
    *(uint4*)&g_xpl[o] = l;
}

// ---------------------------------------------------------------------------
// K0b: pre-pack weights (k-pair-major). 128*640 qkv + 256*256 proj entries.
// ---------------------------------------------------------------------------
__global__ __launch_bounds__(256) void pack_w(
    const float* __restrict__ qw, const float* __restrict__ kvw,
    const float* __restrict__ pw)
{
    const int id = blockIdx.x * 256 + threadIdx.x;
    if (id < 128 * 640) {
        const int kp = id / 640, oc = id % 640;
        const float* wr = (oc < 512) ? qw + (size_t)oc * 256
                                     : kvw + (size_t)(oc - 512) * 256;
        uint32_t h, l;
        pack2(wr[2*kp], wr[2*kp + 1], h, l);
        g_wqh[id] = h; g_wql[id] = l;
    } else {
        const int id2 = id - 128 * 640;
        if (id2 < 256 * 256) {
            const int kp = id2 >> 8, oc = id2 & 255;
            uint32_t h, l;
            pack2(pw[(size_t)oc * 512 + 2*kp], pw[(size_t)oc * 512 + 2*kp + 1], h, l);
            g_wph[id2] = h; g_wpl[id2] = l;
        }
    }
}

// ---------------------------------------------------------------------------
// Scatter store for qkv epilogue.
// ---------------------------------------------------------------------------
__device__ __forceinline__ void store_qkv(int b, int oc, int p, float val,
                                          const float* qb, const float* kvb)
{
    const int i = p >> 10, ssp = p & 1023;
    if (oc < 512) {
        val += qb[oc];
        const int n = oc >> 6, cq = oc & 63;
        g_Q[(((unsigned)(b * 8 + n) * 32 + i) << 16) + (cq << 10) + ssp] = val;
    } else if (oc < 576) {
        val += kvb[oc - 512];
        g_K[(((unsigned)(b * 32 + i)) << 16) + ((oc - 512) << 10) + ssp] = val;
    } else {
        val += kvb[oc - 512];
        const int cv = oc - 576;
        const int h = ssp >> 5, w = ssp & 31;
        const int e2  = ((w & 7) << 6) | cv;
        const int sig = ((h >> 3) << 5) | ((h & 7) << 2) | (w >> 3);
        g_V[(((unsigned)(b * 32 + i)) << 16) + (e2 << 7) + sig] = val;
    }
}

// ---------------------------------------------------------------------------
// Shared GEMM compute step (reads one smem buffer, 3-term split MMA).
// ---------------------------------------------------------------------------
__device__ __forceinline__ void gemm_step(
    const uint32_t* sm, int buf, int wm, int wn, int g, int t,
    float acc[4][4][4])
{
    const uint32_t* Awh = sm + (buf * 4 + 0) * 8 * ROWW;
    const uint32_t* Awl = sm + (buf * 4 + 1) * 8 * ROWW;
    const uint32_t* Bxh = sm + (buf * 4 + 2) * 8 * ROWW;
    const uint32_t* Bxl = sm + (buf * 4 + 3) * 8 * ROWW;

    uint32_t bh[4][2], bl[4][2];
#pragma unroll
    for (int nb = 0; nb < 4; nb++) {
        const int nbase = wn * 32 + nb * 8 + g;
        bh[nb][0] = Bxh[t * ROWW + nbase];       bh[nb][1] = Bxh[(t+4) * ROWW + nbase];
        bl[nb][0] = Bxl[t * ROWW + nbase];       bl[nb][1] = Bxl[(t+4) * ROWW + nbase];
    }
#pragma unroll
    for (int mb = 0; mb < 4; mb++) {
        const int mbase = wm * 64 + mb * 16 + g;
        uint32_t ah[4], al_[4];
        ah[0]  = Awh[t * ROWW + mbase];     ah[1]  = Awh[t * ROWW + mbase + 8];
        ah[2]  = Awh[(t+4) * ROWW + mbase]; ah[3]  = Awh[(t+4) * ROWW + mbase + 8];
        al_[0] = Awl[t * ROWW + mbase];     al_[1] = Awl[t * ROWW + mbase + 8];
        al_[2] = Awl[(t+4) * ROWW + mbase]; al_[3] = Awl[(t+4) * ROWW + mbase + 8];
#pragma unroll
        for (int nb = 0; nb < 4; nb++) {
            MMA16816(acc[mb][nb], ah,  bh[nb]);
            MMA16816(acc[mb][nb], ah,  bl[nb]);
            MMA16816(acc[mb][nb], al_, bh[nb]);
        }
    }
}

// ---------------------------------------------------------------------------
// K1: QKV GEMM. grid(256 p-tiles, 5 mc, 2 b), 256 thr, cp.async double-buffer.
// ---------------------------------------------------------------------------
__global__ __launch_bounds__(256) void qkv_mma(
    const float* __restrict__ qb, const float* __restrict__ kvb)
{
    __shared__ uint32_t sm[2 * 4 * 8 * ROWW];
    const int tid = threadIdx.x, lane = tid & 31, wid = tid >> 5;
    const int wm = wid & 1, wn = wid >> 1;
    const int g = lane >> 2, t = lane & 3;
    const int p0 = blockIdx.x * 128, mc = blockIdx.y, b = blockIdx.z;
    const uint32_t sbase = smem_u32(sm);

    const int r = tid >> 5, c4 = (tid & 31) * 4;
    const uint32_t dst0 = sbase + (r * ROWW + c4) * 4;

    float acc[4][4][4];
#pragma unroll
    for (int mb = 0; mb < 4; mb++)
#pragma unroll
        for (int nb = 0; nb < 4; nb++)
#pragma unroll
            for (int q = 0; q < 4; q++) acc[mb][nb][q] = 0.f;

    // prefetch s=0 into buf 0
    {
        const int wi = r * 640 + mc * 128 + c4;
        const size_t xi = ((size_t)(b * 128 + r) << 15) + p0 + c4;
        CP16(dst0,             &g_wqh[wi]);
        CP16(dst0 + AOFF,      &g_wql[wi]);
        CP16(dst0 + 2*AOFF,    &g_xph[xi]);
        CP16(dst0 + 3*AOFF,    &g_xpl[xi]);
        CP_COMMIT();
    }

    for (int s = 0; s < 16; s++) {
        CP_WAIT0();
        __syncthreads();
        if (s < 15) {
            const int sr = (s + 1) * 8 + r;
            const uint32_t d = dst0 + ((s + 1) & 1) * BUFOFF;
            const int wi = sr * 640 + mc * 128 + c4;
            const size_t xi = ((size_t)(b * 128 + sr) << 15) + p0 + c4;
            CP16(d,          &g_wqh[wi]);
            CP16(d + AOFF,   &g_wql[wi]);
            CP16(d + 2*AOFF, &g_xph[xi]);
            CP16(d + 3*AOFF, &g_xpl[xi]);
            CP_COMMIT();
        }
        gemm_step(sm, s & 1, wm, wn, g, t, acc);
    }

#pragma unroll
    for (int mb = 0; mb < 4; mb++) {
        const int oc_a = mc * 128 + wm * 64 + mb * 16 + g;
#pragma unroll
        for (int nb = 0; nb < 4; nb++) {
            const int pos_a = p0 + wn * 32 + nb * 8 + t * 2;
            store_qkv(b, oc_a,     pos_a,     acc[mb][nb][0], qb, kvb);
            store_qkv(b, oc_a,     pos_a + 1, acc[mb][nb][1], qb, kvb);
            store_qkv(b, oc_a + 8, pos_a,     acc[mb][nb][2], qb, kvb);
            store_qkv(b, oc_a + 8, pos_a + 1, acc[mb][nb][3], qb, kvb);
        }
    }
}

// ---------------------------------------------------------------------------
// K4: proj GEMM. grid(256 p-tiles, 2 mc, 2 b). K=512 -> 32 k-steps.
// ---------------------------------------------------------------------------
__global__ __launch_bounds__(256) void proj_mma(
    const float* __restrict__ pb, const float* __restrict__ ls,
    float* __restrict__ out)
{
    __shared__ uint32_t sm[2 * 4 * 8 * ROWW];
    const int tid = threadIdx.x, lane = tid & 31, wid = tid >> 5;
    const int wm = wid & 1, wn = wid >> 1;
    const int g = lane >> 2, t = lane & 3;
    const int p0 = blockIdx.x * 128, mc = blockIdx.y, b = blockIdx.z;
    const uint32_t sbase = smem_u32(sm);

    const int r = tid >> 5, c4 = (tid & 31) * 4;
    const uint32_t dst0 = sbase + (r * ROWW + c4) * 4;

    float acc[4][4][4];
#pragma unroll
    for (int mb = 0; mb < 4; mb++)
#pragma unroll
        for (int nb = 0; nb < 4; nb++)
#pragma unroll
            for (int q = 0; q < 4; q++) acc[mb][nb][q] = 0.f;

    {
        const int wi = r * 256 + mc * 128 + c4;
        const size_t xi = ((size_t)(b * 256 + r) << 15) + p0 + c4;
        CP16(dst0,          &g_wph[wi]);
        CP16(dst0 + AOFF,   &g_wpl[wi]);
        CP16(dst0 + 2*AOFF, &g_oph[xi]);
        CP16(dst0 + 3*AOFF, &g_opl[xi]);
        CP_COMMIT();
    }

    for (int s = 0; s < 32; s++) {
        CP_WAIT0();
        __syncthreads();
        if (s < 31) {
            const int sr = (s + 1) * 8 + r;
            const uint32_t d = dst0 + ((s + 1) & 1) * BUFOFF;
            const int wi = sr * 256 + mc * 128 + c4;
            const size_t xi = ((size_t)(b * 256 + sr) << 15) + p0 + c4;
            CP16(d,          &g_wph[wi]);
            CP16(d + AOFF,   &g_wpl[wi]);
            CP16(d + 2*AOFF, &g_oph[xi]);
            CP16(d + 3*AOFF, &g_opl[xi]);
            CP_COMMIT();
        }
        gemm_step(sm, s & 1, wm, wn, g, t, acc);
    }

#pragma unroll
    for (int mb = 0; mb < 4; mb++) {
        const int r0 = mc * 128 + wm * 64 + mb * 16 + g;
        const float b0 = pb[r0],     s0 = ls[r0];
        const float b1 = pb[r0 + 8], s1 = ls[r0 + 8];
#pragma unroll
        for (int nb = 0; nb < 4; nb++) {
            const int pos_a = p0 + wn * 32 + nb * 8 + t * 2;
            float* o0 = out + (((size_t)(b * 256 + r0)) << 15) + pos_a;
            float* o1 = out + (((size_t)(b * 256 + r0 + 8)) << 15) + pos_a;
            o0[0] = (acc[mb][nb][0] + b0) * s0;
            o0[1] = (acc[mb][nb][1] + b0) * s0;
            o1[0] = (acc[mb][nb][2] + b1) * s1;
            o1[1] = (acc[mb][nb][3] + b1) * s1;
        }
    }
}

// ---------------------------------------------------------------------------
// K2: attention logits, split over F into 32 chunks of 2048.
// ---------------------------------------------------------------------------
__global__ __launch_bounds__(256) void scores_kernel()
{
    __shared__ __align__(16) float Qs[32][36];
    __shared__ __align__(16) float Ks[32][36];
    const int tid = threadIdx.x;
    const int j0 = (tid & 15) * 2;
    const int i0 = (tid >> 4) * 2;
    const int bn = blockIdx.y;
    const int b  = bn >> 3;
    const unsigned qbase = (unsigned)bn * 32u * 65536u;
    const unsigned kbase = (unsigned)b  * 32u * 65536u;
    const int f0 = blockIdx.x * 2048;
    const int lr = tid >> 3, lc = (tid & 7) * 4;

    float a00 = 0.f, a01 = 0.f, a10 = 0.f, a11 = 0.f;
    for (int fb = f0; fb < f0 + 2048; fb += 32) {
        *(float4*)&Qs[lr][lc] = *(const float4*)&g_Q[qbase + ((unsigned)lr << 16) + fb + lc];
        *(float4*)&Ks[lr][lc] = *(const float4*)&g_K[kbase + ((unsigned)lr << 16) + fb + lc];
        __syncthreads();
#pragma unroll
        for (int k = 0; k < 32; k += 4) {
            float4 q0 = *(const float4*)&Qs[i0][k];
            float4 q1 = *(const float4*)&Qs[i0 + 1][k];
            float4 k0 = *(const float4*)&Ks[j0][k];
            float4 k1 = *(const float4*)&Ks[j0 + 1][k];
            a00 += q0.x*k0.x + q0.y*k0.y + q0.z*k0.z + q0.w*k0.w;
            a01 += q0.x*k1.x + q0.y*k1.y + q0.z*k1.z + q0.w*k1.w;
            a10 += q1.x*k0.x + q1.y*k0.y + q1.z*k0.z + q1.w*k0.w;
            a11 += q1.x*k1.x + q1.y*k1.y + q1.z*k1.z + q1.w*k1.w;
        }
        __syncthreads();
    }
    const unsigned abase = (unsigned)(blockIdx.x * 16 + bn) * 1024u;
    g_Ap[abase +  i0      * 32 + j0    ] = a00;
    g_Ap[abase +  i0      * 32 + j0 + 1] = a01;
    g_Ap[abase + (i0 + 1) * 32 + j0    ] = a10;
    g_Ap[abase + (i0 + 1) * 32 + j0 + 1] = a11;
}

// ---------------------------------------------------------------------------
__global__ __launch_bounds__(1024) void softmax_kernel()
{
    const int bn = blockIdx.x;
    const int tid = threadIdx.x;
    const int i = tid >> 5, j = tid & 31;
    float v = 0.f;
#pragma unroll
    for (int c = 0; c < 32; c++)
        v += g_Ap[((unsigned)(c * 16 + bn) << 10) + (i << 5) + j];
    v *= 0.125f;
    float m = v;
#pragma unroll
    for (int o = 16; o; o >>= 1) m = fmaxf(m, __shfl_xor_sync(0xffffffffu, m, o));
    float e = expf(v - m);
    float s = e;
#pragma unroll
    for (int o = 16; o; o >>= 1) s += __shfl_xor_sync(0xffffffffu, s, o);
    g_A[((unsigned)bn << 10) + (i << 5) + j] = e / s;
}

// ---------------------------------------------------------------------------
// K3: O' = A @ V'. Writes proj input as packed bf16 hi/lo pairs.
// ---------------------------------------------------------------------------
__global__ __launch_bounds__(256) void av_kernel()
{
    __shared__ __align__(16) float As[1024];
    __shared__ float Vs[2][32][128];
    const int tid = threadIdx.x;
    const int bn = blockIdx.y;
    const int b = bn >> 3, n = bn & 7;
    const int e0 = blockIdx.x * 16;

#pragma unroll
    for (int l = 0; l < 4; l++)
        As[l * 256 + tid] = g_A[((unsigned)bn << 10) + l * 256 + tid];
    __syncthreads();

    const int eh  = tid >> 7;
    const int sig = tid & 127;
    const unsigned vbase = ((unsigned)(b * 32)) << 16;

    for (int ei = 0; ei < 16; ei += 2) {
        const int e = e0 + ei + eh;
#pragma unroll
        for (int j = 0; j < 32; j++)
            Vs[eh][j][sig] = g_V[vbase + ((unsigned)j << 16) + (e << 7) + sig];
        __syncthreads();

        float v[32];
#pragma unroll
        for (int j = 0; j < 32; j++) v[j] = Vs[eh][j][sig];

        float acc[32];
#pragma unroll
        for (int i = 0; i < 32; i++) acc[i] = 0.f;
#pragma unroll
        for (int i = 0; i < 32; i++) {
#pragma unroll
            for (int j4 = 0; j4 < 8; j4++) {
                const float4 a = *(const float4*)&As[(i << 5) + j4 * 4];
                acc[i] += a.x * v[j4*4] + a.y * v[j4*4+1] + a.z * v[j4*4+2] + a.w * v[j4*4+3];
            }
        }
        __syncthreads();
#pragma unroll
        for (int i = 0; i < 32; i++) Vs[eh][i][sig] = acc[i];
        __syncthreads();

        const int ep = (e0 + ei) >> 1;
        const size_t obase = ((size_t)(b * 256 + ep) << 15) + (n << 7) + sig;
#pragma unroll
        for (int ii = 0; ii < 16; ii++) {
            const int i = eh * 16 + ii;
            uint32_t h, l;
            pack2(Vs[0][i][sig], Vs[1][i][sig], h, l);
            g_oph[obase + ((size_t)i << 10)] = h;
            g_opl[obase + ((size_t)i << 10)] = l;
        }
        __syncthreads();
    }
}

// ---------------------------------------------------------------------------
extern "C" void kernel_launch(void* const* d_in, const int* in_sizes, int n_in,
                              void* d_out, int out_size)
{
    (void)in_sizes; (void)n_in; (void)out_size;
    const float* x   = (const float*)d_in[0];
    const float* qw  = (const float*)d_in[1];
    const float* qb  = (const float*)d_in[2];
    const float* kvw = (const float*)d_in[3];
    const float* kvb = (const float*)d_in[4];
    const float* pw  = (const float*)d_in[5];
    const float* pb  = (const float*)d_in[6];
    const float* ls  = (const float*)d_in[7];
    float* out = (float*)d_out;

    pack_w        <<<576, 256>>>(qw, kvw, pw);
    cvt_x         <<<dim3(32, 128, 2), 256>>>(x);
    qkv_mma       <<<dim3(256, 5, 2), 256>>>(qb, kvb);
    scores_kernel <<<dim3(32, 16), 256>>>();
    softmax_kernel<<<16, 1024>>>();
    av_kernel     <<<dim3(32, 16), 256>>>();
    proj_mma      <<<dim3(256, 2, 2), 256>>>(pb, ls, out);
}

// round 5
// speedup vs baseline: 2.5031x; 1.2637x over previous
#include <cuda_runtime.h>
#include <cuda_bf16.h>
#include <cstdint>

// ---------------------------------------------------------------------------
// MobileAttention3D: B=2, C=256, D=32, H=W=32, NH=8, KD=VD=64
//
// R5: scores on HMMA. Q/K stored as packed bf16 hi/lo f-pairs by qkv_mma.
//   K0 cvt_x / pack_w ; K1 qkv_mma ; K2 scores_mma ; K2b softmax ; K3 av ;
//   K4 proj_mma
// bf16 2-term split (hi+lo), 3 MMAs per tile, fp32 accum.
// ---------------------------------------------------------------------------

#define NPOS 32768

__device__ float    g_V  [2*32*65536];    // [b][j][e][sigma] (shuffled)
__device__ float    g_Ap [64*16*1024];    // partial logits [fc][bn][i*32+j]
__device__ float    g_A  [16*1024];       // softmaxed attn
__device__ uint32_t g_xph[2*128*32768];   // x bf16-hi pairs [b][cp][p]
__device__ uint32_t g_xpl[2*128*32768];
__device__ uint32_t g_oph[2*256*32768];   // proj-input hi pairs [b][ep][p']
__device__ uint32_t g_opl[2*256*32768];
__device__ uint32_t g_wqh[128*640];       // qkv W hi pairs [kp][oc]
__device__ uint32_t g_wql[128*640];
__device__ uint32_t g_wph[256*256];       // proj W hi pairs [kp][oc]
__device__ uint32_t g_wpl[256*256];
__device__ uint32_t g_Qh [2*8*32*32768];  // Q hi pairs [(bn*32+i)][fp]
__device__ uint32_t g_Ql [2*8*32*32768];
__device__ uint32_t g_Kh [2*32*32768];    // K hi pairs [(b*32+j)][fp]
__device__ uint32_t g_Kl [2*32*32768];

// ---- helpers ----
__device__ __forceinline__ void pack2(float a, float b, uint32_t& hi, uint32_t& lo) {
    __nv_bfloat16 ah = __float2bfloat16(a), bh = __float2bfloat16(b);
    float ar = a - __bfloat162float(ah), br = b - __bfloat162float(bh);
    __nv_bfloat16 al = __float2bfloat16(ar), bl = __float2bfloat16(br);
    hi = (uint32_t)__bfloat16_as_ushort(ah) | ((uint32_t)__bfloat16_as_ushort(bh) << 16);
    lo = (uint32_t)__bfloat16_as_ushort(al) | ((uint32_t)__bfloat16_as_ushort(bl) << 16);
}

__device__ __forceinline__ uint32_t smem_u32(const void* p) {
    uint32_t a;
    asm("{ .reg .u64 t; cvta.to.shared.u64 t, %1; cvt.u32.u64 %0, t; }" : "=r"(a) : "l"(p));
    return a;
}

#define MMA16816(d, a, bf) \
    asm volatile("mma.sync.aligned.m16n8k16.row.col.f32.bf16.bf16.f32 " \
        "{%0,%1,%2,%3}, {%4,%5,%6,%7}, {%8,%9}, {%0,%1,%2,%3};" \
        : "+f"((d)[0]), "+f"((d)[1]), "+f"((d)[2]), "+f"((d)[3]) \
        : "r"((a)[0]), "r"((a)[1]), "r"((a)[2]), "r"((a)[3]), \
          "r"((bf)[0]), "r"((bf)[1]))

#define CP16(dst, src) \
    asm volatile("cp.async.cg.shared.global [%0], [%1], 16;" :: "r"(dst), "l"(src) : "memory")
#define CP_COMMIT() asm volatile("cp.async.commit_group;" ::: "memory")
#define CP_WAIT0()  asm volatile("cp.async.wait_group 0;" ::: "memory")

#define ROWW 136
#define AOFF (8*ROWW*4)
#define BUFOFF (4*AOFF)

// ---------------------------------------------------------------------------
// K0a: convert x to packed bf16 hi/lo pairs over adjacent channels.
// ---------------------------------------------------------------------------
__global__ __launch_bounds__(256) void cvt_x(const float* __restrict__ x)
{
    const int p  = blockIdx.x * 1024 + threadIdx.x * 4;
    const int cp = blockIdx.y;
    const int b  = blockIdx.z;
    const float4 x0 = *(const float4*)&x[((size_t)(b * 256 + 2*cp    ) << 15) + p];
    const float4 x1 = *(const float4*)&x[((size_t)(b * 256 + 2*cp + 1) << 15) + p];
    uint4 h, l;
    pack2(x0.x, x1.x, h.x, l.x);
    pack2(x0.y, x1.y, h.y, l.y);
    pack2(x0.z, x1.z, h.z, l.z);
    pack2(x0.w, x1.w, h.w, l.w);
    const size_t o = ((size_t)(b * 128 + cp) << 15) + p;
    *(uint4*)&g_xph[o] = h;
    *(uint4*)&g_xpl[o] = l;
}

// ---------------------------------------------------------------------------
// K0b: pre-pack weights (k-pair-major).
// ---------------------------------------------------------------------------
__global__ __launch_bounds__(256) void pack_w(
    const float* __restrict__ qw, const float* __restrict__ kvw,
    const float* __restrict__ pw)
{
    const int id = blockIdx.x * 256 + threadIdx.x;
    if (id < 128 * 640) {
        const int kp = id / 640, oc = id % 640;
        const float* wr = (oc < 512) ? qw + (size_t)oc * 256
                                     : kvw + (size_t)(oc - 512) * 256;
        uint32_t h, l;
        pack2(wr[2*kp], wr[2*kp + 1], h, l);
        g_wqh[id] = h; g_wql[id] = l;
    } else {
        const int id2 = id - 128 * 640;
        if (id2 < 256 * 256) {
            const int kp = id2 >> 8, oc = id2 & 255;
            uint32_t h, l;
            pack2(pw[(size_t)oc * 512 + 2*kp], pw[(size_t)oc * 512 + 2*kp + 1], h, l);
            g_wph[id2] = h; g_wpl[id2] = l;
        }
    }
}

// ---------------------------------------------------------------------------
// qkv epilogue pair store: (oc, pos even) + (oc, pos+1).
// ---------------------------------------------------------------------------
__device__ __forceinline__ void store_pair(int b, int oc, int pos,
                                           float v0, float v1,
                                           const float* qb, const float* kvb)
{
    const int i = pos >> 10, s = pos & 1023, sp = s >> 1;
    if (oc < 512) {
        const float bias = qb[oc];
        uint32_t h, l;
        pack2(v0 + bias, v1 + bias, h, l);
        const size_t a = (size_t)((b*8 + (oc >> 6)) * 32 + i) * 32768 + (oc & 63) * 512 + sp;
        g_Qh[a] = h; g_Ql[a] = l;
    } else if (oc < 576) {
        const float bias = kvb[oc - 512];
        uint32_t h, l;
        pack2(v0 + bias, v1 + bias, h, l);
        const size_t a = (size_t)(b*32 + i) * 32768 + (oc - 512) * 512 + sp;
        g_Kh[a] = h; g_Kl[a] = l;
    } else {
        const float bias = kvb[oc - 512];
        const int cv = oc - 576;
        const int hh = s >> 5, w0 = s & 31;          // s even -> same h for s+1
        const int sigbase = ((hh >> 3) << 5) | ((hh & 7) << 2);
        const unsigned vb = ((unsigned)(b * 32 + i)) << 16;
        const int e20 = ((w0 & 7) << 6) | cv;
        const int e21 = (((w0 + 1) & 7) << 6) | cv;
        g_V[vb + (e20 << 7) + sigbase + (w0 >> 3)]       = v0 + bias;
        g_V[vb + (e21 << 7) + sigbase + ((w0 + 1) >> 3)] = v1 + bias;
    }
}

// ---------------------------------------------------------------------------
// Shared GEMM compute step (reads one smem buffer, 3-term split MMA).
// ---------------------------------------------------------------------------
__device__ __forceinline__ void gemm_step(
    const uint32_t* sm, int buf, int wm, int wn, int g, int t,
    float acc[4][4][4])
{
    const uint32_t* Awh = sm + (buf * 4 + 0) * 8 * ROWW;
    const uint32_t* Awl = sm + (buf * 4 + 1) * 8 * ROWW;
    const uint32_t* Bxh = sm + (buf * 4 + 2) * 8 * ROWW;
    const uint32_t* Bxl = sm + (buf * 4 + 3) * 8 * ROWW;

    uint32_t bh[4][2], bl[4][2];
#pragma unroll
    for (int nb = 0; nb < 4; nb++) {
        const int nbase = wn * 32 + nb * 8 + g;
        bh[nb][0] = Bxh[t * ROWW + nbase];       bh[nb][1] = Bxh[(t+4) * ROWW + nbase];
        bl[nb][0] = Bxl[t * ROWW + nbase];       bl[nb][1] = Bxl[(t+4) * ROWW + nbase];
    }
#pragma unroll
    for (int mb = 0; mb < 4; mb++) {
        const int mbase = wm * 64 + mb * 16 + g;
        uint32_t ah[4], al_[4];
        ah[0]  = Awh[t * ROWW + mbase];     ah[1]  = Awh[t * ROWW + mbase + 8];
        ah[2]  = Awh[(t+4) * ROWW + mbase]; ah[3]  = Awh[(t+4) * ROWW + mbase + 8];
        al_[0] = Awl[t * ROWW + mbase];     al_[1] = Awl[t * ROWW + mbase + 8];
        al_[2] = Awl[(t+4) * ROWW + mbase]; al_[3] = Awl[(t+4) * ROWW + mbase + 8];
#pragma unroll
        for (int nb = 0; nb < 4; nb++) {
            MMA16816(acc[mb][nb], ah,  bh[nb]);
            MMA16816(acc[mb][nb], ah,  bl[nb]);
            MMA16816(acc[mb][nb], al_, bh[nb]);
        }
    }
}

// ---------------------------------------------------------------------------
// K1: QKV GEMM. grid(256 p-tiles, 5 mc, 2 b), 256 thr, cp.async double-buffer.
// ---------------------------------------------------------------------------
__global__ __launch_bounds__(256) void qkv_mma(
    const float* __restrict__ qb, const float* __restrict__ kvb)
{
    __shared__ uint32_t sm[2 * 4 * 8 * ROWW];
    const int tid = threadIdx.x, lane = tid & 31, wid = tid >> 5;
    const int wm = wid & 1, wn = wid >> 1;
    const int g = lane >> 2, t = lane & 3;
    const int p0 = blockIdx.x * 128, mc = blockIdx.y, b = blockIdx.z;
    const uint32_t sbase = smem_u32(sm);

    const int r = tid >> 5, c4 = (tid & 31) * 4;
    const uint32_t dst0 = sbase + (r * ROWW + c4) * 4;

    float acc[4][4][4];
#pragma unroll
    for (int mb = 0; mb < 4; mb++)
#pragma unroll
        for (int nb = 0; nb < 4; nb++)
#pragma unroll
            for (int q = 0; q < 4; q++) acc[mb][nb][q] = 0.f;

    {
        const int wi = r * 640 + mc * 128 + c4;
        const size_t xi = ((size_t)(b * 128 + r) << 15) + p0 + c4;
        CP16(dst0,          &g_wqh[wi]);
        CP16(dst0 + AOFF,   &g_wql[wi]);
        CP16(dst0 + 2*AOFF, &g_xph[xi]);
        CP16(dst0 + 3*AOFF, &g_xpl[xi]);
        CP_COMMIT();
    }

    for (int s = 0; s < 16; s++) {
        CP_WAIT0();
        __syncthreads();
        if (s < 15) {
            const int sr = (s + 1) * 8 + r;
            const uint32_t d = dst0 + ((s + 1) & 1) * BUFOFF;
            const int wi = sr * 640 + mc * 128 + c4;
            const size_t xi = ((size_t)(b * 128 + sr) << 15) + p0 + c4;
            CP16(d,          &g_wqh[wi]);
            CP16(d + AOFF,   &g_wql[wi]);
            CP16(d + 2*AOFF, &g_xph[xi]);
            CP16(d + 3*AOFF, &g_xpl[xi]);
            CP_COMMIT();
        }
        gemm_step(sm, s & 1, wm, wn, g, t, acc);
    }

#pragma unroll
    for (int mb = 0; mb < 4; mb++) {
        const int oc_a = mc * 128 + wm * 64 + mb * 16 + g;
#pragma unroll
        for (int nb = 0; nb < 4; nb++) {
            const int pos_a = p0 + wn * 32 + nb * 8 + t * 2;
            store_pair(b, oc_a,     pos_a, acc[mb][nb][0], acc[mb][nb][1], qb, kvb);
            store_pair(b, oc_a + 8, pos_a, acc[mb][nb][2], acc[mb][nb][3], qb, kvb);
        }
    }
}

// ---------------------------------------------------------------------------
// K4: proj GEMM. grid(256 p-tiles, 2 mc, 2 b). K=512 -> 32 k-steps.
// ---------------------------------------------------------------------------
__global__ __launch_bounds__(256) void proj_mma(
    const float* __restrict__ pb, const float* __restrict__ ls,
    float* __restrict__ out)
{
    __shared__ uint32_t sm[2 * 4 * 8 * ROWW];
    const int tid = threadIdx.x, lane = tid & 31, wid = tid >> 5;
    const int wm = wid & 1, wn = wid >> 1;
    const int g = lane >> 2, t = lane & 3;
    const int p0 = blockIdx.x * 128, mc = blockIdx.y, b = blockIdx.z;
    const uint32_t sbase = smem_u32(sm);

    const int r = tid >> 5, c4 = (tid & 31) * 4;
    const uint32_t dst0 = sbase + (r * ROWW + c4) * 4;

    float acc[4][4][4];
#pragma unroll
    for (int mb = 0; mb < 4; mb++)
#pragma unroll
        for (int nb = 0; nb < 4; nb++)
#pragma unroll
            for (int q = 0; q < 4; q++) acc[mb][nb][q] = 0.f;

    {
        const int wi = r * 256 + mc * 128 + c4;
        const size_t xi = ((size_t)(b * 256 + r) << 15) + p0 + c4;
        CP16(dst0,          &g_wph[wi]);
        CP16(dst0 + AOFF,   &g_wpl[wi]);
        CP16(dst0 + 2*AOFF, &g_oph[xi]);
        CP16(dst0 + 3*AOFF, &g_opl[xi]);
        CP_COMMIT();
    }

    for (int s = 0; s < 32; s++) {
        CP_WAIT0();
        __syncthreads();
        if (s < 31) {
            const int sr = (s + 1) * 8 + r;
            const uint32_t d = dst0 + ((s + 1) & 1) * BUFOFF;
            const int wi = sr * 256 + mc * 128 + c4;
            const size_t xi = ((size_t)(b * 256 + sr) << 15) + p0 + c4;
            CP16(d,          &g_wph[wi]);
            CP16(d + AOFF,   &g_wpl[wi]);
            CP16(d + 2*AOFF, &g_oph[xi]);
            CP16(d + 3*AOFF, &g_opl[xi]);
            CP_COMMIT();
        }
        gemm_step(sm, s & 1, wm, wn, g, t, acc);
    }

#pragma unroll
    for (int mb = 0; mb < 4; mb++) {
        const int r0 = mc * 128 + wm * 64 + mb * 16 + g;
        const float b0 = pb[r0],     s0 = ls[r0];
        const float b1 = pb[r0 + 8], s1 = ls[r0 + 8];
#pragma unroll
        for (int nb = 0; nb < 4; nb++) {
            const int pos_a = p0 + wn * 32 + nb * 8 + t * 2;
            float* o0 = out + (((size_t)(b * 256 + r0)) << 15) + pos_a;
            float* o1 = out + (((size_t)(b * 256 + r0 + 8)) << 15) + pos_a;
            o0[0] = (acc[mb][nb][0] + b0) * s0;
            o0[1] = (acc[mb][nb][1] + b0) * s0;
            o1[0] = (acc[mb][nb][2] + b1) * s1;
            o1[1] = (acc[mb][nb][3] + b1) * s1;
        }
    }
}

// ---------------------------------------------------------------------------
// K2: scores via MMA. grid(64 fchunks, 16 bn), 128 thr (4 warps, f-split).
// Each block: 512 f-pairs, 16 staged tiles of 32 pairs (double-buffered).
// Warp covers full 32x32 logit tile for its 8-pair slice per tile.
// ---------------------------------------------------------------------------
#define SROW 36
__global__ __launch_bounds__(128) void scores_mma()
{
    __shared__ uint32_t sm[2 * 4 * 32 * SROW];   // 36864 B
    const int tid = threadIdx.x, lane = tid & 31, w = tid >> 5;
    const int g = lane >> 2, t = lane & 3;
    const int fc = blockIdx.x, bn = blockIdx.y, b = bn >> 3;
    const uint32_t sbase = smem_u32(sm);

    // staging: thread -> row r = tid>>2, quarter q = tid&3 (2 uint4 per array)
    const int r = tid >> 2, q = tid & 3;
    const size_t qrow = ((size_t)(bn * 32 + r)) * 32768 + fc * 512 + q * 8;
    const size_t krow = ((size_t)(b  * 32 + r)) * 32768 + fc * 512 + q * 8;
    const uint32_t dst0 = sbase + (r * SROW + q * 8) * 4;
    const uint32_t A1 = 32 * SROW * 4;           // bytes per array

    float acc[2][4][4];
#pragma unroll
    for (int mi = 0; mi < 2; mi++)
#pragma unroll
        for (int ni = 0; ni < 4; ni++)
#pragma unroll
            for (int z = 0; z < 4; z++) acc[mi][ni][z] = 0.f;

    // prefetch tile 0
    {
        CP16(dst0,        &g_Qh[qrow]);     CP16(dst0 + 16,        &g_Qh[qrow + 4]);
        CP16(dst0 + A1,   &g_Ql[qrow]);     CP16(dst0 + A1 + 16,   &g_Ql[qrow + 4]);
        CP16(dst0 + 2*A1, &g_Kh[krow]);     CP16(dst0 + 2*A1 + 16, &g_Kh[krow + 4]);
        CP16(dst0 + 3*A1, &g_Kl[krow]);     CP16(dst0 + 3*A1 + 16, &g_Kl[krow + 4]);
        CP_COMMIT();
    }

    for (int tl = 0; tl < 16; tl++) {
        CP_WAIT0();
        __syncthreads();
        if (tl < 15) {
            const uint32_t d = dst0 + ((tl + 1) & 1) * (4 * A1);
            const size_t qo = qrow + (tl + 1) * 32, ko = krow + (tl + 1) * 32;
            CP16(d,        &g_Qh[qo]);     CP16(d + 16,        &g_Qh[qo + 4]);
            CP16(d + A1,   &g_Ql[qo]);     CP16(d + A1 + 16,   &g_Ql[qo + 4]);
            CP16(d + 2*A1, &g_Kh[ko]);     CP16(d + 2*A1 + 16, &g_Kh[ko + 4]);
            CP16(d + 3*A1, &g_Kl[ko]);     CP16(d + 3*A1 + 16, &g_Kl[ko + 4]);
            CP_COMMIT();
        }
        // compute on buffer tl&1, this warp's 8-pair slice
        const uint32_t* Qh = sm + ((tl & 1) * 4 + 0) * 32 * SROW;
        const uint32_t* Ql = sm + ((tl & 1) * 4 + 1) * 32 * SROW;
        const uint32_t* Kh = sm + ((tl & 1) * 4 + 2) * 32 * SROW;
        const uint32_t* Kl = sm + ((tl & 1) * 4 + 3) * 32 * SROW;
        const int kp = w * 8;

        uint32_t bh[4][2], bl[4][2];
#pragma unroll
        for (int ni = 0; ni < 4; ni++) {
            const int col = ni * 8 + g;
            bh[ni][0] = Kh[col * SROW + kp + t];
            bh[ni][1] = Kh[col * SROW + kp + t + 4];
            bl[ni][0] = Kl[col * SROW + kp + t];
            bl[ni][1] = Kl[col * SROW + kp + t + 4];
        }
#pragma unroll
        for (int mi = 0; mi < 2; mi++) {
            const int row = mi * 16 + g;
            uint32_t ah[4], al_[4];
            ah[0]  = Qh[row * SROW + kp + t];       ah[1]  = Qh[(row + 8) * SROW + kp + t];
            ah[2]  = Qh[row * SROW + kp + t + 4];   ah[3]  = Qh[(row + 8) * SROW + kp + t + 4];
            al_[0] = Ql[row * SROW + kp + t];       al_[1] = Ql[(row + 8) * SROW + kp + t];
            al_[2] = Ql[row * SROW + kp + t + 4];   al_[3] = Ql[(row + 8) * SROW + kp + t + 4];
#pragma unroll
            for (int ni = 0; ni < 4; ni++) {
                MMA16816(acc[mi][ni], ah,  bh[ni]);
                MMA16816(acc[mi][ni], ah,  bl[ni]);
                MMA16816(acc[mi][ni], al_, bh[ni]);
            }
        }
    }

    // cross-warp reduction via smem (reuse staging buffer)
    __syncthreads();
    float* red = (float*)sm;                     // 4 * 1024 floats
#pragma unroll
    for (int mi = 0; mi < 2; mi++)
#pragma unroll
        for (int ni = 0; ni < 4; ni++) {
            const int i0 = mi * 16 + g, j0 = ni * 8 + t * 2;
            red[w * 1024 + i0 * 32 + j0]           = acc[mi][ni][0];
            red[w * 1024 + i0 * 32 + j0 + 1]       = acc[mi][ni][1];
            red[w * 1024 + (i0 + 8) * 32 + j0]     = acc[mi][ni][2];
            red[w * 1024 + (i0 + 8) * 32 + j0 + 1] = acc[mi][ni][3];
        }
    __syncthreads();
    const unsigned abase = (unsigned)(fc * 16 + bn) * 1024u;
#pragma unroll
    for (int e = 0; e < 8; e++) {
        const int idx = tid * 8 + e;
        g_Ap[abase + idx] = red[idx] + red[1024 + idx] + red[2048 + idx] + red[3072 + idx];
    }
}

// ---------------------------------------------------------------------------
__global__ __launch_bounds__(1024) void softmax_kernel()
{
    const int bn = blockIdx.x;
    const int tid = threadIdx.x;
    const int i = tid >> 5, j = tid & 31;
    float v = 0.f;
#pragma unroll
    for (int c = 0; c < 64; c++)
        v += g_Ap[((unsigned)(c * 16 + bn) << 10) + (i << 5) + j];
    v *= 0.125f;
    float m = v;
#pragma unroll
    for (int o = 16; o; o >>= 1) m = fmaxf(m, __shfl_xor_sync(0xffffffffu, m, o));
    float e = expf(v - m);
    float s = e;
#pragma unroll
    for (int o = 16; o; o >>= 1) s += __shfl_xor_sync(0xffffffffu, s, o);
    g_A[((unsigned)bn << 10) + (i << 5) + j] = e / s;
}

// ---------------------------------------------------------------------------
// K3: O' = A @ V'. Writes proj input as packed bf16 hi/lo pairs.
// ---------------------------------------------------------------------------
__global__ __launch_bounds__(256) void av_kernel()
{
    __shared__ __align__(16) float As[1024];
    __shared__ float Vs[2][32][128];
    const int tid = threadIdx.x;
    const int bn = blockIdx.y;
    const int b = bn >> 3, n = bn & 7;
    const int e0 = blockIdx.x * 16;

#pragma unroll
    for (int l = 0; l < 4; l++)
        As[l * 256 + tid] = g_A[((unsigned)bn << 10) + l * 256 + tid];
    __syncthreads();

    const int eh  = tid >> 7;
    const int sig = tid & 127;
    const unsigned vbase = ((unsigned)(b * 32)) << 16;

    for (int ei = 0; ei < 16; ei += 2) {
        const int e = e0 + ei + eh;
#pragma unroll
        for (int j = 0; j < 32; j++)
            Vs[eh][j][sig] = g_V[vbase + ((unsigned)j << 16) + (e << 7) + sig];
        __syncthreads();

        float v[32];
#pragma unroll
        for (int j = 0; j < 32; j++) v[j] = Vs[eh][j][sig];

        float acc[32];
#pragma unroll
        for (int i = 0; i < 32; i++) acc[i] = 0.f;
#pragma unroll
        for (int i = 0; i < 32; i++) {
#pragma unroll
            for (int j4 = 0; j4 < 8; j4++) {
                const float4 a = *(const float4*)&As[(i << 5) + j4 * 4];
                acc[i] += a.x * v[j4*4] + a.y * v[j4*4+1] + a.z * v[j4*4+2] + a.w * v[j4*4+3];
            }
        }
        __syncthreads();
#pragma unroll
        for (int i = 0; i < 32; i++) Vs[eh][i][sig] = acc[i];
        __syncthreads();

        const int ep = (e0 + ei) >> 1;
        const size_t obase = ((size_t)(b * 256 + ep) << 15) + (n << 7) + sig;
#pragma unroll
        for (int ii = 0; ii < 16; ii++) {
            const int i = eh * 16 + ii;
            uint32_t h, l;
            pack2(Vs[0][i][sig], Vs[1][i][sig], h, l);
            g_oph[obase + ((size_t)i << 10)] = h;
            g_opl[obase + ((size_t)i << 10)] = l;
        }
        __syncthreads();
    }
}

// ---------------------------------------------------------------------------
extern "C" void kernel_launch(void* const* d_in, const int* in_sizes, int n_in,
                              void* d_out, int out_size)
{
    (void)in_sizes; (void)n_in; (void)out_size;
    const float* x   = (const float*)d_in[0];
    const float* qw  = (const float*)d_in[1];
    const float* qb  = (const float*)d_in[2];
    const float* kvw = (const float*)d_in[3];
    const float* kvb = (const float*)d_in[4];
    const float* pw  = (const float*)d_in[5];
    const float* pb  = (const float*)d_in[6];
    const float* ls  = (const float*)d_in[7];
    float* out = (float*)d_out;

    pack_w        <<<576, 256>>>(qw, kvw, pw);
    cvt_x         <<<dim3(32, 128, 2), 256>>>(x);
    qkv_mma       <<<dim3(256, 5, 2), 256>>>(qb, kvb);
    scores_mma    <<<dim3(64, 16), 128>>>();
    softmax_kernel<<<16, 1024>>>();
    av_kernel     <<<dim3(32, 16), 256>>>();
    proj_mma      <<<dim3(256, 2, 2), 256>>>(pb, ls, out);
}